// round 16
// baseline (speedup 1.0000x reference)
#include <cuda_runtime.h>
#include <cuda_bf16.h>
#include <cstdint>

// Resample2d (FlowNet2 bilinear warp), fixed shapes:
//   input1 [B=4, C=64, H=384, W=512] fp32
//   input2 [B=4, 2,    H=384, W=512] fp32  (dx, dy)
//   out    [B=4, C=64, H=384, W=512] fp32
//
// R16 = R15 (best: 112.1us; 2-adjacent-rows-per-block co-location, 3D grid,
// scalar __ldg gathers, warp = 32 consecutive cols of one row) with two
// micro-changes aimed at the residual L1 utilization gap (83.9% vs ~90%):
//   1. channel unroll 4 -> 8 (32 gathers in flight/thread; fewer
//      inter-iteration bubbles in the L1 issue stream)
//   2. floorf/int-cast prologue -> __float2int_rd (shorter pre-memory
//      dependency chain)

#define RS_B 4
#define RS_C 64
#define RS_H 384
#define RS_W 512
#define RS_HW (RS_H * RS_W)
#define RS_CHW (RS_C * RS_HW)

__global__ __launch_bounds__(256) void resample2d_kernel(
    const float* __restrict__ in1,   // [B,C,H,W]
    const float* __restrict__ flow,  // [B,2,H,W]
    float* __restrict__ out)         // [B,C,H,W]
{
    const int cx    = blockIdx.x;              // column chunk 0..3
    const int hpair = blockIdx.y;              // row pair 0..191
    const int b     = blockIdx.z;              // batch 0..3

    const int h   = hpair * 2 + (threadIdx.x >> 7);      // 2 rows per block
    const int col = cx * 128 + (threadIdx.x & 127);
    const int t   = h * RS_W + col;

    const float* flowb = flow + b * 2 * RS_HW;
    const float dx = flowb[t];
    const float dy = flowb[RS_HW + t];

    const float xf = (float)col + dx;
    const float yf = (float)h + dy;
    const int x0i = __float2int_rd(xf);        // floor for |xf| < 2^23
    const int y0i = __float2int_rd(yf);
    const float alpha = xf - __int2float_rn(x0i);
    const float beta  = yf - __int2float_rn(y0i);

    const int xL = min(max(x0i,     0), RS_W - 1);
    const int xR = min(max(x0i + 1, 0), RS_W - 1);
    const int yT = min(max(y0i,     0), RS_H - 1);
    const int yB = min(max(y0i + 1, 0), RS_H - 1);

    const float wTR = alpha * (1.0f - beta);
    const float wBL = (1.0f - alpha) * beta;
    const float wBR = alpha * beta;
    const float wTL = 1.0f - wTR - wBL - wBR;

    const int oTL = yT * RS_W + xL;
    const int oTR = yT * RS_W + xR;
    const int oBL = yB * RS_W + xL;
    const int oBR = yB * RS_W + xR;

    const float* base = in1 + b * RS_CHW;
    float* outp = out + b * RS_CHW + t;

#pragma unroll 8
    for (int c = 0; c < RS_C; ++c) {
        const float* p = base + c * RS_HW;
        const float vTL = __ldg(p + oTL);
        const float vTR = __ldg(p + oTR);
        const float vBL = __ldg(p + oBL);
        const float vBR = __ldg(p + oBR);
        outp[c * RS_HW] = fmaf(wTL, vTL,
                          fmaf(wTR, vTR,
                          fmaf(wBL, vBL,
                               wBR * vBR)));
    }
}

extern "C" void kernel_launch(void* const* d_in, const int* in_sizes, int n_in,
                              void* d_out, int out_size)
{
    const float* in1  = (const float*)d_in[0];
    const float* flow = (const float*)d_in[1];
    float* out = (float*)d_out;

    dim3 grid(RS_W / 128, RS_H / 2, RS_B);   // 4 x 192 x 4 = 3072 blocks
    resample2d_kernel<<<grid, 256>>>(in1, flow, out);
}

// round 17
// speedup vs baseline: 1.0891x; 1.0891x over previous
#include <cuda_runtime.h>
#include <cuda_bf16.h>
#include <cstdint>

// Resample2d (FlowNet2 bilinear warp), fixed shapes:
//   input1 [B=4, C=64, H=384, W=512] fp32
//   input2 [B=4, 2,    H=384, W=512] fp32  (dx, dy)
//   out    [B=4, C=64, H=384, W=512] fp32
//
// R17 = R15 codegen exactly (unroll 4, floorf, scalar __ldg gathers, plain
// store, 256 threads -- the 112.1us best; R16's unroll-8 serialized under
// the 32-reg budget and regressed), with the block->pixel map extended from
// 2 rows x 128 cols to 4 rows x 64 cols. Warp = 32 consecutive columns of
// one row (invariant). 3 of 4 row boundaries now share an L1, removing the
// residual duplicate line fills that the 2-row pairing left at pair
// boundaries (L2 50.9 -> 38.3 with pairing; expect ~33 here).

#define RS_B 4
#define RS_C 64
#define RS_H 384
#define RS_W 512
#define RS_HW (RS_H * RS_W)
#define RS_CHW (RS_C * RS_HW)

__global__ __launch_bounds__(256) void resample2d_kernel(
    const float* __restrict__ in1,   // [B,C,H,W]
    const float* __restrict__ flow,  // [B,2,H,W]
    float* __restrict__ out)         // [B,C,H,W]
{
    const int cx    = blockIdx.x;              // column chunk 0..7 (64 cols)
    const int hquad = blockIdx.y;              // row quad 0..95
    const int b     = blockIdx.z;              // batch 0..3

    const int h   = hquad * 4 + (threadIdx.x >> 6);      // 4 rows per block
    const int col = cx * 64 + (threadIdx.x & 63);
    const int t   = h * RS_W + col;

    const float* flowb = flow + b * 2 * RS_HW;
    const float dx = flowb[t];
    const float dy = flowb[RS_HW + t];

    const float xf = (float)col + dx;
    const float yf = (float)h + dy;
    const float x0 = floorf(xf);
    const float y0 = floorf(yf);
    const float alpha = xf - x0;
    const float beta  = yf - y0;

    const int x0i = (int)x0;
    const int y0i = (int)y0;
    const int xL = min(max(x0i,     0), RS_W - 1);
    const int xR = min(max(x0i + 1, 0), RS_W - 1);
    const int yT = min(max(y0i,     0), RS_H - 1);
    const int yB = min(max(y0i + 1, 0), RS_H - 1);

    const float wTR = alpha * (1.0f - beta);
    const float wBL = (1.0f - alpha) * beta;
    const float wBR = alpha * beta;
    const float wTL = 1.0f - wTR - wBL - wBR;

    const int oTL = yT * RS_W + xL;
    const int oTR = yT * RS_W + xR;
    const int oBL = yB * RS_W + xL;
    const int oBR = yB * RS_W + xR;

    const float* base = in1 + b * RS_CHW;
    float* outp = out + b * RS_CHW + t;

#pragma unroll 4
    for (int c = 0; c < RS_C; ++c) {
        const float* p = base + c * RS_HW;
        const float vTL = __ldg(p + oTL);
        const float vTR = __ldg(p + oTR);
        const float vBL = __ldg(p + oBL);
        const float vBR = __ldg(p + oBR);
        outp[c * RS_HW] = fmaf(wTL, vTL,
                          fmaf(wTR, vTR,
                          fmaf(wBL, vBL,
                               wBR * vBR)));
    }
}

extern "C" void kernel_launch(void* const* d_in, const int* in_sizes, int n_in,
                              void* d_out, int out_size)
{
    const float* in1  = (const float*)d_in[0];
    const float* flow = (const float*)d_in[1];
    float* out = (float*)d_out;

    dim3 grid(RS_W / 64, RS_H / 4, RS_B);   // 8 x 96 x 4 = 3072 blocks
    resample2d_kernel<<<grid, 256>>>(in1, flow, out);
}